// round 14
// baseline (speedup 1.0000x reference)
#include <cuda_runtime.h>
#include <cuda_fp16.h>
#include <cstdint>
#include <cstring>

#define NR 4096
#define NRL ((size_t)4096)
#define SLAB ((size_t)(NR * 128))
#define KSPLIT 8
#define KSLAB 512
#define NCHUNK 16
#define WPR 20        // fp16 tile row stride (words)
#define A32STR 36     // fp32 staging row stride (floats)
#define A32W (128 * A32STR)

// ---------------- device scratch ----------------
__device__ float g_v[4][128];
__device__ float g_c[4];
__device__ float g_bias[128];
__device__ float g_s[4][NR];
__device__ unsigned g_M2e[2];
__device__ unsigned g_ctr[2];                 // work counters (mma, attn)
__device__ __half g_xTh[128 * NR];
__device__ __half g_MTh[2][128 * NR];
__device__ uint32_t g_maskT[2][128 * NR];
__device__ float g_Lx[3][KSPLIT][NR * 128];
__device__ float g_num[2][KSPLIT][NR * 128];
__device__ float g_denp[2][KSPLIT][NR];

// ---------------- helpers ----------------
__device__ __forceinline__ uint32_t h2u(__half2 h) {
    uint32_t u;
    memcpy(&u, &h, 4);
    return u;
}
__device__ __forceinline__ unsigned encf(float f) {
    unsigned u = __float_as_uint(f);
    return (u & 0x80000000u) ? ~u : (u | 0x80000000u);
}
__device__ __forceinline__ float decf(unsigned e) {
    return __uint_as_float((e & 0x80000000u) ? (e & 0x7fffffffu) : ~e);
}
__device__ __forceinline__ uint32_t smem_u32(const void* p) {
    uint32_t a;
    asm("{ .reg .u64 t; cvta.to.shared.u64 t, %1; cvt.u32.u64 %0, t; }" : "=r"(a) : "l"(p));
    return a;
}
__device__ __forceinline__ void cpasync16(uint32_t dst, const void* src) {
    asm volatile("cp.async.cg.shared.global [%0], [%1], 16;" :: "r"(dst), "l"(src) : "memory");
}
#define CP_COMMIT() asm volatile("cp.async.commit_group;" ::: "memory")
#define CP_WAIT2()  asm volatile("cp.async.wait_group 2;" ::: "memory")
#define CP_WAIT1()  asm volatile("cp.async.wait_group 1;" ::: "memory")
#define CP_WAIT0()  asm volatile("cp.async.wait_group 0;" ::: "memory")

#define MMA_F16(c, a, b0, b1) \
    asm volatile("mma.sync.aligned.m16n8k16.row.col.f32.f16.f16.f32 " \
        "{%0,%1,%2,%3}, {%4,%5,%6,%7}, {%8,%9}, {%0,%1,%2,%3};" \
        : "+f"((c)[0]), "+f"((c)[1]), "+f"((c)[2]), "+f"((c)[3]) \
        : "r"((a)[0]), "r"((a)[1]), "r"((a)[2]), "r"((a)[3]), "r"(b0), "r"(b1))

#define LDSM4(r, addr) \
    asm volatile("ldmatrix.sync.aligned.m8n8.x4.shared.b16 {%0,%1,%2,%3}, [%4];" \
        : "=r"((r)[0]), "=r"((r)[1]), "=r"((r)[2]), "=r"((r)[3]) : "r"(addr))

#define NBLOCKS 296

// ---------------- small prep kernels ----------------
__global__ void k_prep(const float* __restrict__ Wi_w, const float* __restrict__ Wi_b,
                       const float* __restrict__ Ws_w, const float* __restrict__ Ws_b,
                       const float* __restrict__ Wh_b,
                       const float* __restrict__ att_irr, const float* __restrict__ att_sol) {
    int c = threadIdx.x;
    float v1i = 0.f, v2i = 0.f, v1s = 0.f, v2s = 0.f;
    for (int j = 0; j < 2; j++)
        for (int o = 0; o < 128; o++) {
            int a = j * 128 + o;
            float wi = Wi_w[(j * 128 + c) * 128 + o];
            float ws = Ws_w[(j * 128 + c) * 128 + o];
            v1i += wi * att_irr[a];  v2i += wi * att_irr[256 + a];
            v1s += ws * att_sol[a];  v2s += ws * att_sol[256 + a];
        }
    g_v[0][c] = v1i; g_v[1][c] = v2i; g_v[2][c] = v1s; g_v[3][c] = v2s;
    float c1i = 0.f, c2i = 0.f, c1s = 0.f, c2s = 0.f;
    for (int j = 0; j < 2; j++) {
        int a = j * 128 + c;
        c1i += Wi_b[a] * att_irr[a];  c2i += Wi_b[a] * att_irr[256 + a];
        c1s += Ws_b[a] * att_sol[a];  c2s += Ws_b[a] * att_sol[256 + a];
    }
    __shared__ float red[4][128];
    red[0][c] = c1i; red[1][c] = c2i; red[2][c] = c1s; red[3][c] = c2s;
    __syncthreads();
    for (int s = 64; s > 0; s >>= 1) {
        if (c < s) for (int q = 0; q < 4; q++) red[q][c] += red[q][c + s];
        __syncthreads();
    }
    if (c < 4) g_c[c] = red[c][0];
    g_bias[c] = Wi_b[c] + Wi_b[128 + c] + Ws_b[c] + Ws_b[128 + c] + Wh_b[c];
}

__global__ void k_scores(const float* __restrict__ x) {
    int wid = threadIdx.x >> 5, lane = threadIdx.x & 31;
    int row = blockIdx.x * 8 + wid;
    float p0 = 0.f, p1 = 0.f, p2 = 0.f, p3 = 0.f;
#pragma unroll
    for (int q = 0; q < 4; q++) {
        int c = q * 32 + lane;
        float xv = x[(size_t)row * 128 + c];
        p0 += xv * g_v[0][c];
        p1 += xv * g_v[1][c];
        p2 += xv * g_v[2][c];
        p3 += xv * g_v[3][c];
    }
#pragma unroll
    for (int s = 16; s > 0; s >>= 1) {
        p0 += __shfl_xor_sync(0xffffffff, p0, s);
        p1 += __shfl_xor_sync(0xffffffff, p1, s);
        p2 += __shfl_xor_sync(0xffffffff, p2, s);
        p3 += __shfl_xor_sync(0xffffffff, p3, s);
    }
    if (lane == 0) {
        g_s[0][row] = p0 + g_c[0];
        g_s[1][row] = p1 + g_c[1];
        g_s[2][row] = p2 + g_c[2];
        g_s[3][row] = p3 + g_c[3];
        atomicMax(&g_M2e[0], encf(p1 + g_c[1]));
        atomicMax(&g_M2e[1], encf(p3 + g_c[3]));
    }
}

__global__ void k_Tx(const float* __restrict__ src, __half* __restrict__ dst) {
    __shared__ float tl[32][129];
    int rb = blockIdx.x * 32, t = threadIdx.x;
    for (int i = t; i < 32 * 128; i += 256) {
        int r = i >> 7, c = i & 127;
        tl[r][c] = src[(size_t)(rb + r) * 128 + c];
    }
    __syncthreads();
    for (int i = t; i < 32 * 128; i += 256) {
        int c = i >> 5, r = i & 31;
        dst[(size_t)c * NRL + rb + r] = __float2half_rn(tl[r][c]);
    }
}

// ---------------- persistent big GEMM ----------------
#define SM_MMA ((3 * A32W + 2 * 128 * WPR + 3 * 128 * WPR) * 4)   // 106496 B
__global__ __launch_bounds__(256, 2) void k_mma_big(const float* __restrict__ Ld,
                                                    const float* __restrict__ Lu,
                                                    const float* __restrict__ P) {
    extern __shared__ uint32_t smw[];
    __shared__ unsigned s_tile;
    uint32_t smb = smem_u32(smw);
    const uint32_t A16w0 = 3 * A32W;
    const uint32_t B16w0 = A16w0 + 2 * 128 * WPR;
    uint32_t Asb[2] = {smb + A16w0 * 4, smb + (A16w0 + 2560) * 4};
    uint32_t Bsb[3] = {smb + B16w0 * 4, smb + (B16w0 + 2560) * 4, smb + (B16w0 + 5120) * 4};

    int tid = threadIdx.x;
    int wid = tid >> 5, lane = tid & 31, gid = lane >> 2, tig = lane & 3;
    int wm = wid >> 1, wn = wid & 1;
    int row = tid >> 1, hb = tid & 1;
    int m8 = lane >> 3, ri = lane & 7;
    uint32_t aoff = (((uint32_t)(m8 & 1) * 8 + ri) * WPR + (m8 >> 1) * 4) * 4;
    uint32_t boff = (((uint32_t)(m8 >> 1) * 8 + ri) * WPR + (m8 & 1) * 4) * 4;

    const unsigned NT = 3u * KSPLIT * 32u;   // 768 tiles
    for (;;) {
        if (tid == 0) s_tile = atomicAdd(&g_ctr[0], 1u);
        __syncthreads();
        unsigned t = s_tile;
        __syncthreads();
        if (t >= NT) break;
        int z = (int)(t >> 8);
        int y = (int)((t & 255u) >> 5);
        int xb = (int)(t & 31u);

        const float* A = (z == 0) ? Ld : ((z == 1) ? Lu : P);
        uint16_t* maskp = (z == 0) ? (uint16_t*)&g_maskT[0][0]
                                   : ((z == 1) ? (uint16_t*)&g_maskT[1][0] : nullptr);
        float* out = &g_Lx[z][y][0];
        int r0 = xb * 128, kb = y * KSLAB, wb = y * NCHUNK;
        size_t arow = (size_t)(r0 + row) * NRL + kb + hb * 16;
        const __half* bsrc = &g_xTh[(size_t)row * NRL + kb + hb * 16];

        float acc[2][8][4];
#pragma unroll
        for (int mi = 0; mi < 2; mi++)
#pragma unroll
            for (int ni = 0; ni < 8; ni++)
#pragma unroll
                for (int q = 0; q < 4; q++) acc[mi][ni][q] = 0.f;

        auto cpAB = [&](int c) {
            int r3 = c % 3;
            uint32_t da = smb + (r3 * A32W + row * A32STR + hb * 16) * 4;
            const float* sa = &A[arow + c * 32];
            cpasync16(da, sa);
            cpasync16(da + 16, sa + 4);
            cpasync16(da + 32, sa + 8);
            cpasync16(da + 48, sa + 12);
            uint32_t db = Bsb[r3] + (row * WPR + hb * 8) * 4;
            cpasync16(db, bsrc + c * 32);
            cpasync16(db + 16, bsrc + c * 32 + 8);
            CP_COMMIT();
        };
        auto convert = [&](int s, int c) {
            int r3 = c % 3;
            const float* a32 = &((const float*)smw)[r3 * A32W + row * A32STR + hb * 16];
            float4 f[4];
#pragma unroll
            for (int j = 0; j < 4; j++) f[j] = *(const float4*)(a32 + 4 * j);
            uint32_t h[8];
            unsigned mb = 0;
#pragma unroll
            for (int j = 0; j < 4; j++) {
                mb |= (f[j].x != 0.f ? 1u : 0u) << (4 * j + 0);
                mb |= (f[j].y != 0.f ? 1u : 0u) << (4 * j + 1);
                mb |= (f[j].z != 0.f ? 1u : 0u) << (4 * j + 2);
                mb |= (f[j].w != 0.f ? 1u : 0u) << (4 * j + 3);
                h[2 * j]     = h2u(__floats2half2_rn(f[j].x, f[j].y));
                h[2 * j + 1] = h2u(__floats2half2_rn(f[j].z, f[j].w));
            }
            uint32_t b = A16w0 + (uint32_t)s * 2560 + row * WPR + hb * 8;
            *(uint4*)&smw[b]     = make_uint4(h[0], h[1], h[2], h[3]);
            *(uint4*)&smw[b + 4] = make_uint4(h[4], h[5], h[6], h[7]);
            if (maskp)
                maskp[(((size_t)(wb + c) * NRL + r0 + row) << 1) | (unsigned)hb] = (uint16_t)mb;
        };
        auto compute = [&](int s, int r3) {
#pragma unroll
            for (int k16 = 0; k16 < 2; k16++) {
                uint32_t a[2][4];
#pragma unroll
                for (int mi = 0; mi < 2; mi++)
                    LDSM4(a[mi], Asb[s] + (((wm * 32 + mi * 16) * WPR) + k16 * 8) * 4 + aoff);
#pragma unroll
                for (int nb = 0; nb < 4; nb++) {
                    uint32_t b[4];
                    LDSM4(b, Bsb[r3] + (((wn * 64 + nb * 16) * WPR) + k16 * 8) * 4 + boff);
                    MMA_F16(acc[0][2 * nb], a[0], b[0], b[1]);
                    MMA_F16(acc[1][2 * nb], a[1], b[0], b[1]);
                    MMA_F16(acc[0][2 * nb + 1], a[0], b[2], b[3]);
                    MMA_F16(acc[1][2 * nb + 1], a[1], b[2], b[3]);
                }
            }
        };

        cpAB(0);
        cpAB(1);
        for (int c = 0; c < NCHUNK; c++) {
            int s = c & 1, r3 = c % 3;
            if (c < NCHUNK - 1) { CP_WAIT1(); } else { CP_WAIT0(); }
            convert(s, c);
            __syncthreads();
            if (c + 2 < NCHUNK) cpAB(c + 2);
            compute(s, r3);
        }
#pragma unroll
        for (int mi = 0; mi < 2; mi++)
#pragma unroll
            for (int ni = 0; ni < 8; ni++) {
                int orow = r0 + wm * 32 + mi * 16 + gid;
                int ocol = wn * 64 + ni * 8 + 2 * tig;
                *(float2*)&out[(size_t)orow * 128 + ocol] = make_float2(acc[mi][ni][0], acc[mi][ni][1]);
                *(float2*)&out[(size_t)(orow + 8) * 128 + ocol] = make_float2(acc[mi][ni][2], acc[mi][ni][3]);
            }
        __syncthreads();
    }
}

// ---------------- persistent masked-softmax attention ----------------
// smem words: A16 2x2560 | B16 3x2560 [5120,12800) | mask 16x128 [12800,14848)
//             s2c [14848,15360) | Bc [15360,15872) | Dc [15872,16384)
#define SM_ATTN (16384 * 4)
__global__ __launch_bounds__(256, 2) void k_attn() {
    extern __shared__ uint32_t smw[];
    __shared__ unsigned s_tile;
    uint32_t smb = smem_u32(smw);
    uint32_t Asb[2] = {smb, smb + 2560 * 4};
    uint32_t Bsb[3] = {smb + 5120 * 4, smb + 7680 * 4, smb + 10240 * 4};
    uint32_t* mask_s = smw + 12800;
    float* s2c = (float*)(smw + 14848);
    float* Bc  = (float*)(smw + 15360);
    float* Dc  = (float*)(smw + 15872);

    int tid = threadIdx.x;
    int wid = tid >> 5, lane = tid & 31, gid = lane >> 2, tig = lane & 3;
    int wm = wid >> 1, wn = wid & 1;
    int row = tid >> 1, hb = tid & 1;
    int m8 = lane >> 3, ri = lane & 7;
    uint32_t aoff = (((uint32_t)(m8 & 1) * 8 + ri) * WPR + (m8 >> 1) * 4) * 4;
    uint32_t boff = (((uint32_t)(m8 >> 1) * 8 + ri) * WPR + (m8 & 1) * 4) * 4;

    const unsigned NT = 2u * KSPLIT * 32u;   // 512 tiles
    for (;;) {
        if (tid == 0) s_tile = atomicAdd(&g_ctr[1], 1u);
        __syncthreads();
        unsigned t = s_tile;
        __syncthreads();
        if (t >= NT) break;
        int mz = (int)(t >> 8);
        int y = (int)((t & 255u) >> 5);
        int xb = (int)(t & 31u);

        float* out = &g_num[mz][y][0];
        int i0 = xb * 128, kb = y * KSLAB, wb = y * NCHUNK;

        // group 0: mask tile (16 wordcols x 128 rows)
#pragma unroll
        for (int k = 0; k < 2; k++) {
            int idx = k * 256 + tid;
            int c = idx >> 5, pos = idx & 31;
            cpasync16(smb + (12800 + c * 128 + pos * 4) * 4,
                      &g_maskT[mz][(size_t)(wb + c) * NRL + i0 + pos * 4]);
        }
        CP_COMMIT();
        for (int i = tid; i < KSLAB; i += 256) {
            float s2 = g_s[2 * mz + 1][kb + i];
            s2c[i] = s2;
            Bc[i]  = expf(s2);
            Dc[i]  = expf(0.2f * s2);
        }
        float M2 = decf(g_M2e[mz]);
        float s1 = g_s[2 * mz][i0 + row];
        float mm = s1 + M2;
        mm = (mm >= 0.f) ? mm : 0.2f * mm;
        float Ai = expf(s1 - mm);
        float Ci = expf(0.2f * s1 - mm);
        float den_t = 0.f;

        const __half* bsrc = &g_MTh[mz][(size_t)row * NRL + kb + hb * 16];
        auto cpB = [&](int buf, int c) {
            uint32_t d = Bsb[buf] + (row * WPR + hb * 8) * 4;
            cpasync16(d, bsrc + c * 32);
            cpasync16(d + 16, bsrc + c * 32 + 8);
            CP_COMMIT();
        };
        cpB(0, 0);
        cpB(1, 1);
        CP_WAIT2();
        __syncthreads();

        float acc[2][8][4];
#pragma unroll
        for (int mi = 0; mi < 2; mi++)
#pragma unroll
            for (int ni = 0; ni < 8; ni++)
#pragma unroll
                for (int q = 0; q < 4; q++) acc[mi][ni][q] = 0.f;

        auto stW = [&](int s, int c) {
            unsigned w32 = mask_s[c * 128 + row];
            unsigned bits = (w32 >> (hb * 16)) & 0xffffu;
            int base = c * 32 + hb * 16;
            uint32_t h[8];
#pragma unroll
            for (int j = 0; j < 4; j++) {
                float4 s2v = *(float4*)&s2c[base + 4 * j];
                float4 Bv  = *(float4*)&Bc[base + 4 * j];
                float4 Dv  = *(float4*)&Dc[base + 4 * j];
                float w0 = ((bits >> (4 * j + 0)) & 1u) ? ((s1 + s2v.x >= 0.f) ? Ai * Bv.x : Ci * Dv.x) : 0.f;
                float w1 = ((bits >> (4 * j + 1)) & 1u) ? ((s1 + s2v.y >= 0.f) ? Ai * Bv.y : Ci * Dv.y) : 0.f;
                float w2 = ((bits >> (4 * j + 2)) & 1u) ? ((s1 + s2v.z >= 0.f) ? Ai * Bv.z : Ci * Dv.z) : 0.f;
                float w3 = ((bits >> (4 * j + 3)) & 1u) ? ((s1 + s2v.w >= 0.f) ? Ai * Bv.w : Ci * Dv.w) : 0.f;
                __half2 p0 = __floats2half2_rn(w0, w1);
                __half2 p1 = __floats2half2_rn(w2, w3);
                den_t += __low2float(p0) + __high2float(p0) + __low2float(p1) + __high2float(p1);
                h[2 * j] = h2u(p0);
                h[2 * j + 1] = h2u(p1);
            }
            uint32_t b = (uint32_t)s * 2560 + row * WPR + hb * 8;
            *(uint4*)&smw[b]     = make_uint4(h[0], h[1], h[2], h[3]);
            *(uint4*)&smw[b + 4] = make_uint4(h[4], h[5], h[6], h[7]);
        };
        auto compute = [&](int s, int buf) {
#pragma unroll
            for (int k16 = 0; k16 < 2; k16++) {
                uint32_t a[2][4];
#pragma unroll
                for (int mi = 0; mi < 2; mi++)
                    LDSM4(a[mi], Asb[s] + (((wm * 32 + mi * 16) * WPR) + k16 * 8) * 4 + aoff);
#pragma unroll
                for (int nb = 0; nb < 4; nb++) {
                    uint32_t b[4];
                    LDSM4(b, Bsb[buf] + (((wn * 64 + nb * 16) * WPR) + k16 * 8) * 4 + boff);
                    MMA_F16(acc[0][2 * nb], a[0], b[0], b[1]);
                    MMA_F16(acc[1][2 * nb], a[1], b[0], b[1]);
                    MMA_F16(acc[0][2 * nb + 1], a[0], b[2], b[3]);
                    MMA_F16(acc[1][2 * nb + 1], a[1], b[2], b[3]);
                }
            }
        };

        for (int c = 0; c < NCHUNK; c++) {
            int s = c & 1, buf = c % 3;
            if (c < NCHUNK - 1) { CP_WAIT1(); } else { CP_WAIT0(); }
            stW(s, c);
            __syncthreads();
            if (c + 2 < NCHUNK) cpB((c + 2) % 3, c + 2);
            compute(s, buf);
        }
#pragma unroll
        for (int mi = 0; mi < 2; mi++)
#pragma unroll
            for (int ni = 0; ni < 8; ni++) {
                int orow = i0 + wm * 32 + mi * 16 + gid;
                int ocol = wn * 64 + ni * 8 + 2 * tig;
                *(float2*)&out[(size_t)orow * 128 + ocol] = make_float2(acc[mi][ni][0], acc[mi][ni][1]);
                *(float2*)&out[(size_t)(orow + 8) * 128 + ocol] = make_float2(acc[mi][ni][2], acc[mi][ni][3]);
            }
        float den_pair = den_t + __shfl_xor_sync(0xffffffffu, den_t, 1);
        if (hb == 0) g_denp[mz][y][i0 + row] = den_pair;
        __syncthreads();
    }
}

// ---------------- unified epilogue GEMMs (K=128), slab-summing ----------------
__global__ __launch_bounds__(256) void k_gemm2u(const float* __restrict__ x,
                                                const float* __restrict__ Wi_w,
                                                const float* __restrict__ Ws_w,
                                                const float* __restrict__ Wh_w,
                                                float* __restrict__ zout,
                                                __half* __restrict__ MTh) {
    __shared__ float A1s[32][33];
    __shared__ float A2s[32][33];
    __shared__ float W1s[32][128];
    __shared__ float W2s[32][128];
    __shared__ __half stg[32][136];
    int zz = blockIdx.y;
    const float* A1;
    const float* A2 = nullptr;
    const float* W1;
    const float* W2 = nullptr;
    __half* CT = nullptr;
    int ns1, ns2;
    if (zz == 0) { A1 = x; ns1 = 1; A2 = &g_Lx[0][0][0]; ns2 = KSPLIT; W1 = Wi_w; W2 = Wi_w + 16384; CT = MTh; }
    else if (zz == 1) { A1 = x; ns1 = 1; A2 = &g_Lx[1][0][0]; ns2 = KSPLIT; W1 = Ws_w; W2 = Ws_w + 16384; CT = MTh + 128 * NRL; }
    else { A1 = &g_Lx[2][0][0]; ns1 = KSPLIT; ns2 = 0; W1 = Wh_w; }

    int tid = threadIdx.x;
    int bm = blockIdx.x * 32;
    int trow = (tid >> 5) * 4;
    int tcol = (tid & 31) * 4;
    int am = tid >> 3;
    int ak = (tid & 7) * 4;
    int wr = tid >> 5;
    int wc = (tid & 31) * 4;
    float acc[4][4];
#pragma unroll
    for (int r = 0; r < 4; r++)
#pragma unroll
        for (int c = 0; c < 4; c++) acc[r][c] = 0.f;

    for (int kk = 0; kk < 128; kk += 32) {
        size_t aidx = (size_t)(bm + am) * 128 + kk + ak;
        float4 a1 = *(const float4*)&A1[aidx];
        for (int p = 1; p < ns1; p++) {
            float4 t = *(const float4*)&A1[p * SLAB + aidx];
            a1.x += t.x; a1.y += t.y; a1.z += t.z; a1.w += t.w;
        }
        A1s[ak + 0][am] = a1.x; A1s[ak + 1][am] = a1.y; A1s[ak + 2][am] = a1.z; A1s[ak + 3][am] = a1.w;
        if (ns2 > 0) {
            float4 a2 = *(const float4*)&A2[aidx];
            for (int p = 1; p < ns2; p++) {
                float4 t = *(const float4*)&A2[p * SLAB + aidx];
                a2.x += t.x; a2.y += t.y; a2.z += t.z; a2.w += t.w;
            }
            A2s[ak + 0][am] = a2.x; A2s[ak + 1][am] = a2.y; A2s[ak + 2][am] = a2.z; A2s[ak + 3][am] = a2.w;
        }
#pragma unroll
        for (int q = 0; q < 4; q++) {
            *(float4*)&W1s[wr + q * 8][wc] = *(const float4*)&W1[(size_t)(kk + wr + q * 8) * 128 + wc];
            if (ns2 > 0)
                *(float4*)&W2s[wr + q * 8][wc] = *(const float4*)&W2[(size_t)(kk + wr + q * 8) * 128 + wc];
        }
        __syncthreads();
#pragma unroll
        for (int k = 0; k < 32; k++) {
            float a1f[4], a2f[4];
#pragma unroll
            for (int r = 0; r < 4; r++) {
                a1f[r] = A1s[k][trow + r];
                a2f[r] = A2s[k][trow + r];
            }
            float4 w1v = *(float4*)&W1s[k][tcol];
            float4 w2v = *(float4*)&W2s[k][tcol];
#pragma unroll
            for (int r = 0; r < 4; r++) {
                acc[r][0] += a1f[r] * w1v.x;
                acc[r][1] += a1f[r] * w1v.y;
                acc[r][2] += a1f[r] * w1v.z;
                acc[r][3] += a1f[r] * w1v.w;
                if (ns2 > 0) {
                    acc[r][0] += a2f[r] * w2v.x;
                    acc[r][1] += a2f[r] * w2v.y;
                    acc[r][2] += a2f[r] * w2v.z;
                    acc[r][3] += a2f[r] * w2v.w;
                }
            }
        }
        __syncthreads();
    }
    if (zz != 2) {
#pragma unroll
        for (int r = 0; r < 4; r++)
#pragma unroll
            for (int c = 0; c < 4; c++)
                stg[trow + r][tcol + c] = __float2half_rn(acc[r][c]);
        __syncthreads();
        int col = tid >> 1, r0 = (tid & 1) * 16;
        __half hv[16];
#pragma unroll
        for (int j = 0; j < 16; j++) hv[j] = stg[r0 + j][col];
        *(uint4*)&CT[(size_t)col * NRL + bm + r0] = *(uint4*)&hv[0];
        *(uint4*)&CT[(size_t)col * NRL + bm + r0 + 8] = *(uint4*)&hv[8];
    } else {
#pragma unroll
        for (int r = 0; r < 4; r++) {
            float4 o = make_float4(acc[r][0], acc[r][1], acc[r][2], acc[r][3]);
            o.x += g_bias[tcol + 0];
            o.y += g_bias[tcol + 1];
            o.z += g_bias[tcol + 2];
            o.w += g_bias[tcol + 3];
            *(float4*)&zout[(size_t)(bm + trow + r) * 128 + tcol] = o;
        }
    }
}

__global__ void k_final(float* __restrict__ z) {
    int idx = blockIdx.x * 256 + threadIdx.x;
    int i = idx >> 7;
    float d0 = 0.f, d1 = 0.f, n0 = 0.f, n1 = 0.f;
#pragma unroll
    for (int p = 0; p < KSPLIT; p++) {
        d0 += g_denp[0][p][i];
        d1 += g_denp[1][p][i];
        n0 += g_num[0][p][idx];
        n1 += g_num[1][p][idx];
    }
    if (!(d0 > 0.f)) d0 = 1.f;
    if (!(d1 > 0.f)) d1 = 1.f;
    z[idx] += n0 / d0 + n1 / d1;
}

// ---------------- host launcher ----------------
extern "C" void kernel_launch(void* const* d_in, const int* in_sizes, int n_in,
                              void* d_out, int out_size) {
    const float* x       = (const float*)d_in[0];
    const float* Lu      = (const float*)d_in[1];
    const float* Ld      = (const float*)d_in[2];
    const float* P       = (const float*)d_in[3];
    const float* Wi_w    = (const float*)d_in[4];
    const float* Wi_b    = (const float*)d_in[5];
    const float* Ws_w    = (const float*)d_in[6];
    const float* Ws_b    = (const float*)d_in[7];
    const float* Wh_w    = (const float*)d_in[8];
    const float* Wh_b    = (const float*)d_in[9];
    const float* att_irr = (const float*)d_in[10];
    const float* att_sol = (const float*)d_in[11];
    float* z = (float*)d_out;

    cudaFuncSetAttribute((const void*)k_mma_big, cudaFuncAttributeMaxDynamicSharedMemorySize, SM_MMA);
    cudaFuncSetAttribute((const void*)k_attn, cudaFuncAttributeMaxDynamicSharedMemorySize, SM_ATTN);

    unsigned *p_M2e, *p_ctr;
    __half *p_xTh, *p_MTh;
    cudaGetSymbolAddress((void**)&p_M2e, g_M2e);
    cudaGetSymbolAddress((void**)&p_ctr, g_ctr);
    cudaGetSymbolAddress((void**)&p_xTh, g_xTh);
    cudaGetSymbolAddress((void**)&p_MTh, g_MTh);

    cudaMemsetAsync(p_M2e, 0, 2 * sizeof(unsigned));
    cudaMemsetAsync(p_ctr, 0, 2 * sizeof(unsigned));
    k_Tx<<<NR / 32, 256>>>(x, p_xTh);
    k_prep<<<1, 128>>>(Wi_w, Wi_b, Ws_w, Ws_b, Wh_b, att_irr, att_sol);
    k_scores<<<NR / 8, 256>>>(x);
    k_mma_big<<<NBLOCKS, 256, SM_MMA>>>(Ld, Lu, P);
    k_gemm2u<<<dim3(NR / 32, 3), 256>>>(x, Wi_w, Ws_w, Wh_w, z, p_MTh);
    k_attn<<<NBLOCKS, 256, SM_ATTN>>>();
    k_final<<<NR * 128 / 256, 256>>>(z);
}

// round 16
// speedup vs baseline: 1.1224x; 1.1224x over previous
#include <cuda_runtime.h>
#include <cuda_fp16.h>
#include <cstdint>
#include <cstring>

#define NR 4096
#define NRL ((size_t)4096)
#define SLAB ((size_t)(NR * 128))
#define KSPLIT 4
#define KSLAB 1024
#define NCHUNK 32
#define WPR 20        // fp16 tile row stride (words); conflict-free for ldmatrix
#define A32STR 36     // fp32 staging row stride (floats)
#define A32W (128 * A32STR)   // 4608 words per fp32 tile

// ---------------- device scratch ----------------
__device__ float g_v[4][128];
__device__ float g_c[4];
__device__ float g_bias[128];
__device__ float g_s[4][NR];
__device__ unsigned g_M2e[2];
__device__ __half g_xTh[128 * NR];
__device__ __half g_MTh[2][128 * NR];
__device__ uint32_t g_maskT[2][128 * NR];     // [wordcol][row]
__device__ float g_Lx[3][KSPLIT][NR * 128];
__device__ float g_num[2][KSPLIT][NR * 128];
__device__ float g_denp[2][KSPLIT][NR];

// ---------------- helpers ----------------
__device__ __forceinline__ uint32_t h2u(__half2 h) {
    uint32_t u;
    memcpy(&u, &h, 4);
    return u;
}
__device__ __forceinline__ unsigned encf(float f) {
    unsigned u = __float_as_uint(f);
    return (u & 0x80000000u) ? ~u : (u | 0x80000000u);
}
__device__ __forceinline__ float decf(unsigned e) {
    return __uint_as_float((e & 0x80000000u) ? (e & 0x7fffffffu) : ~e);
}
__device__ __forceinline__ uint32_t smem_u32(const void* p) {
    uint32_t a;
    asm("{ .reg .u64 t; cvta.to.shared.u64 t, %1; cvt.u32.u64 %0, t; }" : "=r"(a) : "l"(p));
    return a;
}
__device__ __forceinline__ void cpasync16(uint32_t dst, const void* src) {
    asm volatile("cp.async.cg.shared.global [%0], [%1], 16;" :: "r"(dst), "l"(src) : "memory");
}
#define CP_COMMIT() asm volatile("cp.async.commit_group;" ::: "memory")
#define CP_WAIT2()  asm volatile("cp.async.wait_group 2;" ::: "memory")
#define CP_WAIT1()  asm volatile("cp.async.wait_group 1;" ::: "memory")
#define CP_WAIT0()  asm volatile("cp.async.wait_group 0;" ::: "memory")

#define MMA_F16(c, a, b0, b1) \
    asm volatile("mma.sync.aligned.m16n8k16.row.col.f32.f16.f16.f32 " \
        "{%0,%1,%2,%3}, {%4,%5,%6,%7}, {%8,%9}, {%0,%1,%2,%3};" \
        : "+f"((c)[0]), "+f"((c)[1]), "+f"((c)[2]), "+f"((c)[3]) \
        : "r"((a)[0]), "r"((a)[1]), "r"((a)[2]), "r"((a)[3]), "r"(b0), "r"(b1))

#define LDSM4(r, addr) \
    asm volatile("ldmatrix.sync.aligned.m8n8.x4.shared.b16 {%0,%1,%2,%3}, [%4];" \
        : "=r"((r)[0]), "=r"((r)[1]), "=r"((r)[2]), "=r"((r)[3]) : "r"(addr))

// ---------------- small prep kernels ----------------
__global__ void k_prep(const float* __restrict__ Wi_w, const float* __restrict__ Wi_b,
                       const float* __restrict__ Ws_w, const float* __restrict__ Ws_b,
                       const float* __restrict__ Wh_b,
                       const float* __restrict__ att_irr, const float* __restrict__ att_sol) {
    int c = threadIdx.x;
    float v1i = 0.f, v2i = 0.f, v1s = 0.f, v2s = 0.f;
    for (int j = 0; j < 2; j++)
        for (int o = 0; o < 128; o++) {
            int a = j * 128 + o;
            float wi = Wi_w[(j * 128 + c) * 128 + o];
            float ws = Ws_w[(j * 128 + c) * 128 + o];
            v1i += wi * att_irr[a];  v2i += wi * att_irr[256 + a];
            v1s += ws * att_sol[a];  v2s += ws * att_sol[256 + a];
        }
    g_v[0][c] = v1i; g_v[1][c] = v2i; g_v[2][c] = v1s; g_v[3][c] = v2s;
    float c1i = 0.f, c2i = 0.f, c1s = 0.f, c2s = 0.f;
    for (int j = 0; j < 2; j++) {
        int a = j * 128 + c;
        c1i += Wi_b[a] * att_irr[a];  c2i += Wi_b[a] * att_irr[256 + a];
        c1s += Ws_b[a] * att_sol[a];  c2s += Ws_b[a] * att_sol[256 + a];
    }
    __shared__ float red[4][128];
    red[0][c] = c1i; red[1][c] = c2i; red[2][c] = c1s; red[3][c] = c2s;
    __syncthreads();
    for (int s = 64; s > 0; s >>= 1) {
        if (c < s) for (int q = 0; q < 4; q++) red[q][c] += red[q][c + s];
        __syncthreads();
    }
    if (c < 4) g_c[c] = red[c][0];
    g_bias[c] = Wi_b[c] + Wi_b[128 + c] + Ws_b[c] + Ws_b[128 + c] + Wh_b[c];
}

__global__ void k_scores(const float* __restrict__ x) {
    int wid = threadIdx.x >> 5, lane = threadIdx.x & 31;
    int row = blockIdx.x * 8 + wid;
    float p0 = 0.f, p1 = 0.f, p2 = 0.f, p3 = 0.f;
#pragma unroll
    for (int q = 0; q < 4; q++) {
        int c = q * 32 + lane;
        float xv = x[(size_t)row * 128 + c];
        p0 += xv * g_v[0][c];
        p1 += xv * g_v[1][c];
        p2 += xv * g_v[2][c];
        p3 += xv * g_v[3][c];
    }
#pragma unroll
    for (int s = 16; s > 0; s >>= 1) {
        p0 += __shfl_xor_sync(0xffffffff, p0, s);
        p1 += __shfl_xor_sync(0xffffffff, p1, s);
        p2 += __shfl_xor_sync(0xffffffff, p2, s);
        p3 += __shfl_xor_sync(0xffffffff, p3, s);
    }
    if (lane == 0) {
        g_s[0][row] = p0 + g_c[0];
        g_s[1][row] = p1 + g_c[1];
        g_s[2][row] = p2 + g_c[2];
        g_s[3][row] = p3 + g_c[3];
        atomicMax(&g_M2e[0], encf(p1 + g_c[1]));
        atomicMax(&g_M2e[1], encf(p3 + g_c[3]));
    }
}

__global__ void k_Tx(const float* __restrict__ src, __half* __restrict__ dst) {
    __shared__ float tl[32][129];
    int rb = blockIdx.x * 32, t = threadIdx.x;
    for (int i = t; i < 32 * 128; i += 256) {
        int r = i >> 7, c = i & 127;
        tl[r][c] = src[(size_t)(rb + r) * 128 + c];
    }
    __syncthreads();
    for (int i = t; i < 32 * 128; i += 256) {
        int c = i >> 5, r = i & 31;
        dst[(size_t)c * NRL + rb + r] = __float2half_rn(tl[r][c]);
    }
}

// ---------------- big GEMM: coalesced cp.async fp32 stage -> cvt -> fp16 mma ----------------
#define SM_MMA ((3 * A32W + 2 * 128 * WPR + 3 * 128 * WPR) * 4)   // 106496 B
__global__ __launch_bounds__(256, 2) void k_mma_big(const float* __restrict__ Ld,
                                                    const float* __restrict__ Lu,
                                                    const float* __restrict__ P) {
    extern __shared__ uint32_t smw[];
    uint32_t smb = smem_u32(smw);
    const uint32_t A16w0 = 3 * A32W;
    const uint32_t B16w0 = A16w0 + 2 * 128 * WPR;
    uint32_t Asb[2] = {smb + A16w0 * 4, smb + (A16w0 + 2560) * 4};
    uint32_t Bsb[3] = {smb + B16w0 * 4, smb + (B16w0 + 2560) * 4, smb + (B16w0 + 5120) * 4};

    int tid = threadIdx.x;
    int wid = tid >> 5, lane = tid & 31, gid = lane >> 2, tig = lane & 3;
    int wm = wid >> 1, wn = wid & 1;
    int row = tid >> 1, hb = tid & 1;
    int m8 = lane >> 3, ri = lane & 7;
    uint32_t aoff = (((uint32_t)(m8 & 1) * 8 + ri) * WPR + (m8 >> 1) * 4) * 4;
    uint32_t boff = (((uint32_t)(m8 >> 1) * 8 + ri) * WPR + (m8 & 1) * 4) * 4;

    int z = blockIdx.z;
    const float* A = (z == 0) ? Ld : ((z == 1) ? Lu : P);
    uint16_t* maskp = (z == 0) ? (uint16_t*)&g_maskT[0][0] : ((z == 1) ? (uint16_t*)&g_maskT[1][0] : nullptr);
    float* out = &g_Lx[z][blockIdx.y][0];
    int r0 = blockIdx.x * 128, kb = blockIdx.y * KSLAB, wb = blockIdx.y * NCHUNK;

    float acc[2][8][4];
#pragma unroll
    for (int mi = 0; mi < 2; mi++)
#pragma unroll
        for (int ni = 0; ni < 8; ni++)
#pragma unroll
            for (int q = 0; q < 4; q++) acc[mi][ni][q] = 0.f;

    // Coalesced staging: consecutive lanes load consecutive 16B of the same row.
    auto cpAB = [&](int c) {
        int r3 = c % 3;
#pragma unroll
        for (int j = 0; j < 4; j++) {
            int idx = j * 256 + tid;
            int ar = idx >> 3, ap = idx & 7;
            cpasync16(smb + (uint32_t)(r3 * A32W + ar * A32STR + ap * 4) * 4,
                      &A[(size_t)(r0 + ar) * NRL + kb + c * 32 + ap * 4]);
        }
#pragma unroll
        for (int j = 0; j < 2; j++) {
            int idx = j * 256 + tid;
            int br = idx >> 2, bp = idx & 3;
            cpasync16(Bsb[r3] + (uint32_t)(br * WPR + bp * 4) * 4,
                      &g_xTh[(size_t)br * NRL + kb + c * 32 + bp * 8]);
        }
        CP_COMMIT();
    };
    auto convert = [&](int s, int c) {
        int r3 = c % 3;
        const float* a32 = &((const float*)smw)[r3 * A32W + row * A32STR + hb * 16];
        float4 f[4];
#pragma unroll
        for (int j = 0; j < 4; j++) f[j] = *(const float4*)(a32 + 4 * j);
        uint32_t h[8];
        unsigned mb = 0;
#pragma unroll
        for (int j = 0; j < 4; j++) {
            mb |= (f[j].x != 0.f ? 1u : 0u) << (4 * j + 0);
            mb |= (f[j].y != 0.f ? 1u : 0u) << (4 * j + 1);
            mb |= (f[j].z != 0.f ? 1u : 0u) << (4 * j + 2);
            mb |= (f[j].w != 0.f ? 1u : 0u) << (4 * j + 3);
            h[2 * j]     = h2u(__floats2half2_rn(f[j].x, f[j].y));
            h[2 * j + 1] = h2u(__floats2half2_rn(f[j].z, f[j].w));
        }
        uint32_t b = A16w0 + (uint32_t)s * 2560 + row * WPR + hb * 8;
        *(uint4*)&smw[b]     = make_uint4(h[0], h[1], h[2], h[3]);
        *(uint4*)&smw[b + 4] = make_uint4(h[4], h[5], h[6], h[7]);
        if (maskp)
            maskp[(((size_t)(wb + c) * NRL + r0 + row) << 1) | (unsigned)hb] = (uint16_t)mb;
    };
    auto compute = [&](int s, int r3) {
#pragma unroll
        for (int k16 = 0; k16 < 2; k16++) {
            uint32_t a[2][4];
#pragma unroll
            for (int mi = 0; mi < 2; mi++)
                LDSM4(a[mi], Asb[s] + (((wm * 32 + mi * 16) * WPR) + k16 * 8) * 4 + aoff);
#pragma unroll
            for (int nb = 0; nb < 4; nb++) {
                uint32_t b[4];
                LDSM4(b, Bsb[r3] + (((wn * 64 + nb * 16) * WPR) + k16 * 8) * 4 + boff);
                MMA_F16(acc[0][2 * nb], a[0], b[0], b[1]);
                MMA_F16(acc[1][2 * nb], a[1], b[0], b[1]);
                MMA_F16(acc[0][2 * nb + 1], a[0], b[2], b[3]);
                MMA_F16(acc[1][2 * nb + 1], a[1], b[2], b[3]);
            }
        }
    };

    cpAB(0);
    cpAB(1);
    for (int c = 0; c < NCHUNK; c++) {
        int s = c & 1, r3 = c % 3;
        if (c < NCHUNK - 1) { CP_WAIT1(); } else { CP_WAIT0(); }
        __syncthreads();   // chunk-c staging from ALL threads visible (convert reads cross-thread data)
        convert(s, c);
        __syncthreads();   // A16[s] visible to all; also fences WAR for cpAB(c+2)
        if (c + 2 < NCHUNK) cpAB(c + 2);
        compute(s, r3);
    }
#pragma unroll
    for (int mi = 0; mi < 2; mi++)
#pragma unroll
        for (int ni = 0; ni < 8; ni++) {
            int orow = r0 + wm * 32 + mi * 16 + gid;
            int ocol = wn * 64 + ni * 8 + 2 * tig;
            *(float2*)&out[(size_t)orow * 128 + ocol] = make_float2(acc[mi][ni][0], acc[mi][ni][1]);
            *(float2*)&out[(size_t)(orow + 8) * 128 + ocol] = make_float2(acc[mi][ni][2], acc[mi][ni][3]);
        }
}

// ---------------- fused masked-softmax attention: mask-driven, coalesced B ----------------
// smem words: A16 2x2560 [0,5120) | B16 3x2560 [5120,12800) | mask 32x128 [12800,16896)
//             s2c [16896,17920) | Bc [17920,18944) | Dc [18944,19968)
#define SM_ATTN (19968 * 4)
__global__ __launch_bounds__(256, 2) void k_attn() {
    extern __shared__ uint32_t smw[];
    uint32_t smb = smem_u32(smw);
    uint32_t Asb[2] = {smb, smb + 2560 * 4};
    uint32_t Bsb[3] = {smb + 5120 * 4, smb + 7680 * 4, smb + 10240 * 4};
    uint32_t* mask_s = smw + 12800;
    float* s2c = (float*)(smw + 16896);
    float* Bc  = (float*)(smw + 17920);
    float* Dc  = (float*)(smw + 18944);

    int tid = threadIdx.x;
    int wid = tid >> 5, lane = tid & 31, gid = lane >> 2, tig = lane & 3;
    int wm = wid >> 1, wn = wid & 1;
    int row = tid >> 1, hb = tid & 1;
    int m8 = lane >> 3, ri = lane & 7;
    uint32_t aoff = (((uint32_t)(m8 & 1) * 8 + ri) * WPR + (m8 >> 1) * 4) * 4;
    uint32_t boff = (((uint32_t)(m8 >> 1) * 8 + ri) * WPR + (m8 & 1) * 4) * 4;

    int mz = blockIdx.z;
    float* out = &g_num[mz][blockIdx.y][0];
    int i0 = blockIdx.x * 128, kb = blockIdx.y * KSLAB, wb = blockIdx.y * NCHUNK;

    // group 0: mask tile (32 wordcols x 128 rows = 16KB), lane-coalesced
#pragma unroll
    for (int k = 0; k < 4; k++) {
        int idx = k * 256 + tid;
        int c = idx >> 5, pos = idx & 31;
        cpasync16(smb + (12800 + c * 128 + pos * 4) * 4,
                  &g_maskT[mz][(size_t)(wb + c) * NRL + i0 + pos * 4]);
    }
    CP_COMMIT();
    for (int i = tid; i < KSLAB; i += 256) {
        float s2 = g_s[2 * mz + 1][kb + i];
        s2c[i] = s2;
        Bc[i]  = expf(s2);
        Dc[i]  = expf(0.2f * s2);
    }
    float M2 = decf(g_M2e[mz]);
    float s1 = g_s[2 * mz][i0 + row];
    float mm = s1 + M2;
    mm = (mm >= 0.f) ? mm : 0.2f * mm;
    float Ai = expf(s1 - mm);
    float Ci = expf(0.2f * s1 - mm);
    float den_t = 0.f;

    auto cpB = [&](int buf, int c) {
#pragma unroll
        for (int j = 0; j < 2; j++) {
            int idx = j * 256 + tid;
            int br = idx >> 2, bp = idx & 3;
            cpasync16(Bsb[buf] + (uint32_t)(br * WPR + bp * 4) * 4,
                      &g_MTh[mz][(size_t)br * NRL + kb + c * 32 + bp * 8]);
        }
        CP_COMMIT();
    };
    cpB(0, 0);
    cpB(1, 1);
    CP_WAIT2();
    __syncthreads();

    float acc[2][8][4];
#pragma unroll
    for (int mi = 0; mi < 2; mi++)
#pragma unroll
        for (int ni = 0; ni < 8; ni++)
#pragma unroll
            for (int q = 0; q < 4; q++) acc[mi][ni][q] = 0.f;

    auto stW = [&](int s, int c) {
        unsigned w32 = mask_s[c * 128 + row];
        unsigned bits = (w32 >> (hb * 16)) & 0xffffu;
        int base = c * 32 + hb * 16;
        uint32_t h[8];
#pragma unroll
        for (int j = 0; j < 4; j++) {
            float4 s2v = *(float4*)&s2c[base + 4 * j];
            float4 Bv  = *(float4*)&Bc[base + 4 * j];
            float4 Dv  = *(float4*)&Dc[base + 4 * j];
            float w0 = ((bits >> (4 * j + 0)) & 1u) ? ((s1 + s2v.x >= 0.f) ? Ai * Bv.x : Ci * Dv.x) : 0.f;
            float w1 = ((bits >> (4 * j + 1)) & 1u) ? ((s1 + s2v.y >= 0.f) ? Ai * Bv.y : Ci * Dv.y) : 0.f;
            float w2 = ((bits >> (4 * j + 2)) & 1u) ? ((s1 + s2v.z >= 0.f) ? Ai * Bv.z : Ci * Dv.z) : 0.f;
            float w3 = ((bits >> (4 * j + 3)) & 1u) ? ((s1 + s2v.w >= 0.f) ? Ai * Bv.w : Ci * Dv.w) : 0.f;
            __half2 p0 = __floats2half2_rn(w0, w1);
            __half2 p1 = __floats2half2_rn(w2, w3);
            den_t += __low2float(p0) + __high2float(p0) + __low2float(p1) + __high2float(p1);
            h[2 * j] = h2u(p0);
            h[2 * j + 1] = h2u(p1);
        }
        uint32_t b = (uint32_t)s * 2560 + row * WPR + hb * 8;
        *(uint4*)&smw[b]     = make_uint4(h[0], h[1], h[2], h[3]);
        *(uint4*)&smw[b + 4] = make_uint4(h[4], h[5], h[6], h[7]);
    };
    auto compute = [&](int s, int buf) {
#pragma unroll
        for (int k16 = 0; k16 < 2; k16++) {
            uint32_t a[2][4];
#pragma unroll
            for (int mi = 0; mi < 2; mi++)
                LDSM4(a[mi], Asb[s] + (((wm * 32 + mi * 16) * WPR) + k16 * 8) * 4 + aoff);
#pragma unroll
            for (int nb = 0; nb < 4; nb++) {
                uint32_t b[4];
                LDSM4(b, Bsb[buf] + (((wn * 64 + nb * 16) * WPR) + k16 * 8) * 4 + boff);
                MMA_F16(acc[0][2 * nb], a[0], b[0], b[1]);
                MMA_F16(acc[1][2 * nb], a[1], b[0], b[1]);
                MMA_F16(acc[0][2 * nb + 1], a[0], b[2], b[3]);
                MMA_F16(acc[1][2 * nb + 1], a[1], b[2], b[3]);
            }
        }
    };

    for (int c = 0; c < NCHUNK; c++) {
        int s = c & 1, buf = c % 3;
        if (c < NCHUNK - 1) { CP_WAIT1(); } else { CP_WAIT0(); }
        stW(s, c);
        __syncthreads();   // B16[buf] (cross-thread) + A16[s] visible before compute
        if (c + 2 < NCHUNK) cpB((c + 2) % 3, c + 2);
        compute(s, buf);
    }
#pragma unroll
    for (int mi = 0; mi < 2; mi++)
#pragma unroll
        for (int ni = 0; ni < 8; ni++) {
            int orow = i0 + wm * 32 + mi * 16 + gid;
            int ocol = wn * 64 + ni * 8 + 2 * tig;
            *(float2*)&out[(size_t)orow * 128 + ocol] = make_float2(acc[mi][ni][0], acc[mi][ni][1]);
            *(float2*)&out[(size_t)(orow + 8) * 128 + ocol] = make_float2(acc[mi][ni][2], acc[mi][ni][3]);
        }
    float den_pair = den_t + __shfl_xor_sync(0xffffffffu, den_t, 1);
    if (hb == 0) g_denp[mz][blockIdx.y][i0 + row] = den_pair;
}

// ---------------- unified epilogue GEMMs (K=128), slab-summing A operands ----------------
__global__ __launch_bounds__(256) void k_gemm2u(const float* __restrict__ x,
                                                const float* __restrict__ Wi_w,
                                                const float* __restrict__ Ws_w,
                                                const float* __restrict__ Wh_w,
                                                float* __restrict__ zout,
                                                __half* __restrict__ MTh) {
    __shared__ float A1s[32][33];
    __shared__ float A2s[32][33];
    __shared__ float W1s[32][128];
    __shared__ float W2s[32][128];
    __shared__ __half stg[32][136];
    int zz = blockIdx.y;
    const float* A1;
    const float* A2 = nullptr;
    const float* W1;
    const float* W2 = nullptr;
    __half* CT = nullptr;
    int ns1, ns2;
    if (zz == 0) { A1 = x; ns1 = 1; A2 = &g_Lx[0][0][0]; ns2 = KSPLIT; W1 = Wi_w; W2 = Wi_w + 16384; CT = MTh; }
    else if (zz == 1) { A1 = x; ns1 = 1; A2 = &g_Lx[1][0][0]; ns2 = KSPLIT; W1 = Ws_w; W2 = Ws_w + 16384; CT = MTh + 128 * NRL; }
    else { A1 = &g_Lx[2][0][0]; ns1 = KSPLIT; ns2 = 0; W1 = Wh_w; }

    int tid = threadIdx.x;
    int bm = blockIdx.x * 32;
    int trow = (tid >> 5) * 4;
    int tcol = (tid & 31) * 4;
    int am = tid >> 3;
    int ak = (tid & 7) * 4;
    int wr = tid >> 5;
    int wc = (tid & 31) * 4;
    float acc[4][4];
#pragma unroll
    for (int r = 0; r < 4; r++)
#pragma unroll
        for (int c = 0; c < 4; c++) acc[r][c] = 0.f;

    for (int kk = 0; kk < 128; kk += 32) {
        size_t aidx = (size_t)(bm + am) * 128 + kk + ak;
        float4 a1 = *(const float4*)&A1[aidx];
        for (int p = 1; p < ns1; p++) {
            float4 t = *(const float4*)&A1[p * SLAB + aidx];
            a1.x += t.x; a1.y += t.y; a1.z += t.z; a1.w += t.w;
        }
        A1s[ak + 0][am] = a1.x; A1s[ak + 1][am] = a1.y; A1s[ak + 2][am] = a1.z; A1s[ak + 3][am] = a1.w;
        if (ns2 > 0) {
            float4 a2 = *(const float4*)&A2[aidx];
            for (int p = 1; p < ns2; p++) {
                float4 t = *(const float4*)&A2[p * SLAB + aidx];
                a2.x += t.x; a2.y += t.y; a2.z += t.z; a2.w += t.w;
            }
            A2s[ak + 0][am] = a2.x; A2s[ak + 1][am] = a2.y; A2s[ak + 2][am] = a2.z; A2s[ak + 3][am] = a2.w;
        }
#pragma unroll
        for (int q = 0; q < 4; q++) {
            *(float4*)&W1s[wr + q * 8][wc] = *(const float4*)&W1[(size_t)(kk + wr + q * 8) * 128 + wc];
            if (ns2 > 0)
                *(float4*)&W2s[wr + q * 8][wc] = *(const float4*)&W2[(size_t)(kk + wr + q * 8) * 128 + wc];
        }
        __syncthreads();
#pragma unroll
        for (int k = 0; k < 32; k++) {
            float a1f[4], a2f[4];
#pragma unroll
            for (int r = 0; r < 4; r++) {
                a1f[r] = A1s[k][trow + r];
                a2f[r] = A2s[k][trow + r];
            }
            float4 w1v = *(float4*)&W1s[k][tcol];
            float4 w2v = *(float4*)&W2s[k][tcol];
#pragma unroll
            for (int r = 0; r < 4; r++) {
                acc[r][0] += a1f[r] * w1v.x;
                acc[r][1] += a1f[r] * w1v.y;
                acc[r][2] += a1f[r] * w1v.z;
                acc[r][3] += a1f[r] * w1v.w;
                if (ns2 > 0) {
                    acc[r][0] += a2f[r] * w2v.x;
                    acc[r][1] += a2f[r] * w2v.y;
                    acc[r][2] += a2f[r] * w2v.z;
                    acc[r][3] += a2f[r] * w2v.w;
                }
            }
        }
        __syncthreads();
    }
    if (zz != 2) {
#pragma unroll
        for (int r = 0; r < 4; r++)
#pragma unroll
            for (int c = 0; c < 4; c++)
                stg[trow + r][tcol + c] = __float2half_rn(acc[r][c]);
        __syncthreads();
        int col = tid >> 1, r0 = (tid & 1) * 16;
        __half hv[16];
#pragma unroll
        for (int j = 0; j < 16; j++) hv[j] = stg[r0 + j][col];
        *(uint4*)&CT[(size_t)col * NRL + bm + r0] = *(uint4*)&hv[0];
        *(uint4*)&CT[(size_t)col * NRL + bm + r0 + 8] = *(uint4*)&hv[8];
    } else {
#pragma unroll
        for (int r = 0; r < 4; r++) {
            float4 o = make_float4(acc[r][0], acc[r][1], acc[r][2], acc[r][3]);
            o.x += g_bias[tcol + 0];
            o.y += g_bias[tcol + 1];
            o.z += g_bias[tcol + 2];
            o.w += g_bias[tcol + 3];
            *(float4*)&zout[(size_t)(bm + trow + r) * 128 + tcol] = o;
        }
    }
}

__global__ void k_final(float* __restrict__ z) {
    int idx = blockIdx.x * 256 + threadIdx.x;
    int i = idx >> 7;
    float d0 = 0.f, d1 = 0.f, n0 = 0.f, n1 = 0.f;
#pragma unroll
    for (int p = 0; p < KSPLIT; p++) {
        d0 += g_denp[0][p][i];
        d1 += g_denp[1][p][i];
        n0 += g_num[0][p][idx];
        n1 += g_num[1][p][idx];
    }
    if (!(d0 > 0.f)) d0 = 1.f;
    if (!(d1 > 0.f)) d1 = 1.f;
    z[idx] += n0 / d0 + n1 / d1;
}

// ---------------- host launcher ----------------
extern "C" void kernel_launch(void* const* d_in, const int* in_sizes, int n_in,
                              void* d_out, int out_size) {
    const float* x       = (const float*)d_in[0];
    const float* Lu      = (const float*)d_in[1];
    const float* Ld      = (const float*)d_in[2];
    const float* P       = (const float*)d_in[3];
    const float* Wi_w    = (const float*)d_in[4];
    const float* Wi_b    = (const float*)d_in[5];
    const float* Ws_w    = (const float*)d_in[6];
    const float* Ws_b    = (const float*)d_in[7];
    const float* Wh_w    = (const float*)d_in[8];
    const float* Wh_b    = (const float*)d_in[9];
    const float* att_irr = (const float*)d_in[10];
    const float* att_sol = (const float*)d_in[11];
    float* z = (float*)d_out;

    cudaFuncSetAttribute((const void*)k_mma_big, cudaFuncAttributeMaxDynamicSharedMemorySize, SM_MMA);
    cudaFuncSetAttribute((const void*)k_attn, cudaFuncAttributeMaxDynamicSharedMemorySize, SM_ATTN);

    unsigned* p_M2e;
    __half *p_xTh, *p_MTh;
    cudaGetSymbolAddress((void**)&p_M2e, g_M2e);
    cudaGetSymbolAddress((void**)&p_xTh, g_xTh);
    cudaGetSymbolAddress((void**)&p_MTh, g_MTh);

    cudaMemsetAsync(p_M2e, 0, 2 * sizeof(unsigned));
    k_Tx<<<NR / 32, 256>>>(x, p_xTh);
    k_prep<<<1, 128>>>(Wi_w, Wi_b, Ws_w, Ws_b, Wh_b, att_irr, att_sol);
    k_scores<<<NR / 8, 256>>>(x);
    k_mma_big<<<dim3(NR / 128, KSPLIT, 3), 256, SM_MMA>>>(Ld, Lu, P);
    k_gemm2u<<<dim3(NR / 32, 3), 256>>>(x, Wi_w, Ws_w, Wh_w, z, p_MTh);
    k_attn<<<dim3(NR / 128, KSPLIT, 2), 256, SM_ATTN>>>();
    k_final<<<NR * 128 / 256, 256>>>(z);
}